// round 9
// baseline (speedup 1.0000x reference)
#include <cuda_runtime.h>
#include <cstdint>

// out[r][c] = in[(2r+1)*8192 + (2c+1)], out is 4096x4096 f32.
//
// 256-bit loads (sm_100+): one ld.global.v8.f32 per output float4.
// Input floats 8j..8j+7 (32B aligned, sector-exact) -> odd elements
// y,w of each half -> output float4 (out cols 4j..4j+3), STG.128.
// 4 independent v8 loads front-batched per thread (MLP=4).

__device__ __forceinline__ void ldg256_cs(const float* p, float* v) {
    asm volatile(
        "ld.global.cs.v8.f32 {%0,%1,%2,%3,%4,%5,%6,%7}, [%8];"
        : "=f"(v[0]), "=f"(v[1]), "=f"(v[2]), "=f"(v[3]),
          "=f"(v[4]), "=f"(v[5]), "=f"(v[6]), "=f"(v[7])
        : "l"(p));
}

__global__ void downsample_odd_v8(const float* __restrict__ in,
                                  float4* __restrict__ out) {
    // 256 threads per output row (1024 float4 per row / 4 per thread)
    int idx = blockIdx.x * blockDim.x + threadIdx.x;
    int r = idx >> 8;          // output row
    int g = idx & 255;         // float4-group within row

    // input row 2r+1 (8192 floats); thread's 4 chunks at stride 256*8 floats
    const float* src = in + (long long)(2 * r + 1) * 8192;
    float4* dst = out + (long long)r * 1024;

    float a[8], b[8], c[8], d[8];
    ldg256_cs(src + (g          ) * 8, a);
    ldg256_cs(src + (g + 256    ) * 8, b);
    ldg256_cs(src + (g + 512    ) * 8, c);
    ldg256_cs(src + (g + 768    ) * 8, d);

    dst[g]        = make_float4(a[1], a[3], a[5], a[7]);
    dst[g + 256]  = make_float4(b[1], b[3], b[5], b[7]);
    dst[g + 512]  = make_float4(c[1], c[3], c[5], c[7]);
    dst[g + 768]  = make_float4(d[1], d[3], d[5], d[7]);
}

extern "C" void kernel_launch(void* const* d_in, const int* in_sizes, int n_in,
                              void* d_out, int out_size) {
    const float* in = (const float*)d_in[0];
    float4* out = (float4*)d_out;

    const long long total = 4096LL * 256;   // 1,048,576 threads
    int threads = 256;
    int blocks = (int)(total / threads);    // 4096
    downsample_odd_v8<<<blocks, threads>>>(in, out);
}